// round 3
// baseline (speedup 1.0000x reference)
#include <cuda_runtime.h>

#define BB 8
#define TT 2560
#define FF 229
#define C1N 5
#define C2N 11
#define F2 114
#define F3 57
#define FEAT 627       // C2N * F3
#define OFN 88
#define MCN 48
#define GN 8
#define DH 6
#define KW 31
#define PADW 15
#define BNEPS 1e-5f
#define FRAME_ELEMS (BB*TT*OFN)

// ---------------- scratch (device globals; no allocation allowed) ----------
__device__ float g_y1[(size_t)BB*C1N*TT*FF];   // conv1 out  (B,C1,T,F)
__device__ float g_y2[(size_t)BB*C1N*TT*F2];   // conv2+pool (B,C1,T,F2)
__device__ float g_x627[(size_t)BB*TT*FEAT];   // conv3+pool, transposed to (B*T, 627)
__device__ float g_x88[(size_t)BB*TT*OFN];     // fc out (B*T, 88)
__device__ float g_qkv[(size_t)BB*TT*144];     // q|k|v (B*T, 144)
__device__ float g_out48[(size_t)BB*TT*MCN];   // attention out (B*T, 48)

// ---------------- K1: conv1(1->5) + BN + ReLU ------------------------------
__global__ void k_conv1(const float* __restrict__ spec, const float* __restrict__ w,
                        const float* __restrict__ cb, const float* __restrict__ bg,
                        const float* __restrict__ bbt, const float* __restrict__ bm,
                        const float* __restrict__ bv) {
    __shared__ float sw[C1N*9];
    __shared__ float ssc[C1N], sbi[C1N];
    for (int i = threadIdx.x; i < C1N*9; i += blockDim.x) sw[i] = w[i];
    if (threadIdx.x < C1N) {
        float sc = bg[threadIdx.x] * rsqrtf(bv[threadIdx.x] + BNEPS);
        ssc[threadIdx.x] = sc;
        sbi[threadIdx.x] = (cb[threadIdx.x] - bm[threadIdx.x]) * sc + bbt[threadIdx.x];
    }
    __syncthreads();
    int idx = blockIdx.x * blockDim.x + threadIdx.x;
    if (idx >= BB*TT*FF) return;
    int f = idx % FF;
    int t = (idx / FF) % TT;
    int b = idx / (FF*TT);
    const float* sp = spec + (size_t)b * TT * FF;
    float in[3][3];
    #pragma unroll
    for (int dt = 0; dt < 3; dt++) {
        int tt = t + dt - 1;
        #pragma unroll
        for (int df = 0; df < 3; df++) {
            int ff = f + df - 1;
            in[dt][df] = (tt >= 0 && tt < TT && ff >= 0 && ff < FF) ? sp[tt*FF + ff] : 0.f;
        }
    }
    #pragma unroll
    for (int c = 0; c < C1N; c++) {
        float acc = 0.f;
        #pragma unroll
        for (int k9 = 0; k9 < 9; k9++)
            acc = fmaf(in[k9/3][k9%3], sw[c*9 + k9], acc);
        float val = acc * ssc[c] + sbi[c];
        g_y1[(((size_t)b*C1N + c)*TT + t)*FF + f] = fmaxf(val, 0.f);
    }
}

// ---------------- K2: conv2(5->5) + BN + ReLU + maxpool(W/2) ---------------
__global__ void k_conv2pool(const float* __restrict__ w, const float* __restrict__ cb,
                            const float* __restrict__ bg, const float* __restrict__ bbt,
                            const float* __restrict__ bm, const float* __restrict__ bv) {
    __shared__ float sw[C1N*C1N*9];
    __shared__ float ssc[C1N], sbi[C1N];
    for (int i = threadIdx.x; i < C1N*C1N*9; i += blockDim.x) sw[i] = w[i];
    if (threadIdx.x < C1N) {
        float sc = bg[threadIdx.x] * rsqrtf(bv[threadIdx.x] + BNEPS);
        ssc[threadIdx.x] = sc;
        sbi[threadIdx.x] = (cb[threadIdx.x] - bm[threadIdx.x]) * sc + bbt[threadIdx.x];
    }
    __syncthreads();
    int idx = blockIdx.x * blockDim.x + threadIdx.x;
    if (idx >= BB*TT*F2) return;
    int fp = idx % F2;
    int t = (idx / F2) % TT;
    int b = idx / (F2*TT);
    float acc0[C1N], acc1[C1N];
    #pragma unroll
    for (int c = 0; c < C1N; c++) { acc0[c] = 0.f; acc1[c] = 0.f; }
    #pragma unroll
    for (int ci = 0; ci < C1N; ci++) {
        const float* base = g_y1 + ((size_t)b*C1N + ci)*TT*FF;
        float patch[3][4];
        #pragma unroll
        for (int dt = 0; dt < 3; dt++) {
            int tt = t + dt - 1;
            #pragma unroll
            for (int df = 0; df < 4; df++) {
                int ff = 2*fp + df - 1;
                patch[dt][df] = (tt >= 0 && tt < TT && ff >= 0 && ff < FF) ? base[tt*FF + ff] : 0.f;
            }
        }
        #pragma unroll
        for (int co = 0; co < C1N; co++) {
            const float* wp = &sw[(co*C1N + ci)*9];
            #pragma unroll
            for (int dt = 0; dt < 3; dt++) {
                #pragma unroll
                for (int df = 0; df < 3; df++) {
                    float wv_ = wp[dt*3 + df];
                    acc0[co] = fmaf(patch[dt][df],     wv_, acc0[co]);
                    acc1[co] = fmaf(patch[dt][df + 1], wv_, acc1[co]);
                }
            }
        }
    }
    #pragma unroll
    for (int co = 0; co < C1N; co++) {
        float v0 = fmaxf(acc0[co]*ssc[co] + sbi[co], 0.f);
        float v1 = fmaxf(acc1[co]*ssc[co] + sbi[co], 0.f);
        g_y2[(((size_t)b*C1N + co)*TT + t)*F2 + fp] = fmaxf(v0, v1);
    }
}

// ---------------- K3: conv3(5->11) + BN + ReLU + maxpool + transpose -------
__global__ void k_conv3pool(const float* __restrict__ w, const float* __restrict__ cb,
                            const float* __restrict__ bg, const float* __restrict__ bbt,
                            const float* __restrict__ bm, const float* __restrict__ bv) {
    __shared__ float sw[C2N*C1N*9];   // 495 floats -- MUST be loaded with a strided loop
    __shared__ float ssc[C2N], sbi[C2N];
    for (int i = threadIdx.x; i < C2N*C1N*9; i += blockDim.x) sw[i] = w[i];
    if (threadIdx.x < C2N) {
        float sc = bg[threadIdx.x] * rsqrtf(bv[threadIdx.x] + BNEPS);
        ssc[threadIdx.x] = sc;
        sbi[threadIdx.x] = (cb[threadIdx.x] - bm[threadIdx.x]) * sc + bbt[threadIdx.x];
    }
    __syncthreads();
    int idx = blockIdx.x * blockDim.x + threadIdx.x;
    if (idx >= BB*TT*F3) return;
    int fp = idx % F3;
    int t = (idx / F3) % TT;
    int b = idx / (F3*TT);
    float acc0[C2N], acc1[C2N];
    #pragma unroll
    for (int c = 0; c < C2N; c++) { acc0[c] = 0.f; acc1[c] = 0.f; }
    #pragma unroll
    for (int ci = 0; ci < C1N; ci++) {
        const float* base = g_y2 + ((size_t)b*C1N + ci)*TT*F2;
        float patch[3][4];
        #pragma unroll
        for (int dt = 0; dt < 3; dt++) {
            int tt = t + dt - 1;
            #pragma unroll
            for (int df = 0; df < 4; df++) {
                int ff = 2*fp + df - 1;
                patch[dt][df] = (tt >= 0 && tt < TT && ff >= 0 && ff < F2) ? base[tt*F2 + ff] : 0.f;
            }
        }
        #pragma unroll
        for (int co = 0; co < C2N; co++) {
            const float* wp = &sw[(co*C1N + ci)*9];
            #pragma unroll
            for (int dt = 0; dt < 3; dt++) {
                #pragma unroll
                for (int df = 0; df < 3; df++) {
                    float wv_ = wp[dt*3 + df];
                    acc0[co] = fmaf(patch[dt][df],     wv_, acc0[co]);
                    acc1[co] = fmaf(patch[dt][df + 1], wv_, acc1[co]);
                }
            }
        }
    }
    #pragma unroll
    for (int co = 0; co < C2N; co++) {
        float v0 = fmaxf(acc0[co]*ssc[co] + sbi[co], 0.f);
        float v1 = fmaxf(acc1[co]*ssc[co] + sbi[co], 0.f);
        // layout: (b*T + t, co*F3 + fp) -> matches transpose+reshape of reference
        g_x627[((size_t)b*TT + t)*FEAT + co*F3 + fp] = fmaxf(v0, v1);
    }
}

// ---------------- K4: fc GEMM  (20480 x 627) @ (627 x 88)^T + bias ---------
// block: 128 rows x 88 cols; 256 threads; thread tile 4 rows x 11 cols
__global__ void k_fc(const float* __restrict__ W, const float* __restrict__ bias) {
    __shared__ float sA[128][33];
    __shared__ float sW[88][33];
    int m0 = blockIdx.x * 128;
    int tx = threadIdx.x % 8;    // col group: cols tx + 8*j, j=0..10
    int ty = threadIdx.x / 8;    // 0..31 -> rows 4*ty .. 4*ty+3
    float acc[4][11];
    #pragma unroll
    for (int r = 0; r < 4; r++)
        #pragma unroll
        for (int j = 0; j < 11; j++) acc[r][j] = 0.f;

    for (int k0 = 0; k0 < FEAT; k0 += 32) {
        for (int i = threadIdx.x; i < 128*32; i += 256) {
            int rr = i >> 5, kk = i & 31;
            int kg = k0 + kk;
            sA[rr][kk] = (kg < FEAT) ? g_x627[(size_t)(m0 + rr)*FEAT + kg] : 0.f;
        }
        for (int i = threadIdx.x; i < 88*32; i += 256) {
            int n = i >> 5, kk = i & 31;
            int kg = k0 + kk;
            sW[n][kk] = (kg < FEAT) ? W[n*FEAT + kg] : 0.f;
        }
        __syncthreads();
        #pragma unroll 8
        for (int kk = 0; kk < 32; kk++) {
            float a[4];
            #pragma unroll
            for (int r = 0; r < 4; r++) a[r] = sA[4*ty + r][kk];
            #pragma unroll
            for (int j = 0; j < 11; j++) {
                float wv_ = sW[tx + 8*j][kk];
                #pragma unroll
                for (int r = 0; r < 4; r++)
                    acc[r][j] = fmaf(a[r], wv_, acc[r][j]);
            }
        }
        __syncthreads();
    }
    #pragma unroll
    for (int r = 0; r < 4; r++)
        #pragma unroll
        for (int j = 0; j < 11; j++)
            g_x88[(size_t)(m0 + 4*ty + r)*OFN + tx + 8*j] = acc[r][j] + bias[tx + 8*j];
}

// ---------------- K5: qkv GEMM (20480 x 88) @ (88 x 144) -------------------
// block: 32 rows x 144 cols; 256 threads; thread tile 2 rows x 9 cols
__global__ void k_qkv(const float* __restrict__ wq, const float* __restrict__ wk,
                      const float* __restrict__ wv) {
    __shared__ float sA[32][45];
    __shared__ float sW[144][45];
    int m0 = blockIdx.x * 32;
    int tx = threadIdx.x % 16;   // cols tx + 16*j, j=0..8
    int ty = threadIdx.x / 16;   // 0..15 -> rows 2*ty, 2*ty+1
    float acc[2][9];
    #pragma unroll
    for (int r = 0; r < 2; r++)
        #pragma unroll
        for (int j = 0; j < 9; j++) acc[r][j] = 0.f;

    for (int k0 = 0; k0 < OFN; k0 += 44) {
        for (int i = threadIdx.x; i < 32*44; i += 256) {
            int rr = i / 44, kk = i % 44;
            sA[rr][kk] = g_x88[(size_t)(m0 + rr)*OFN + k0 + kk];
        }
        for (int i = threadIdx.x; i < 144*44; i += 256) {
            int n = i / 44, kk = i % 44;
            int kg = k0 + kk;
            float val;
            if (n < 48)      val = wq[n*OFN + kg];
            else if (n < 96) val = wk[(n - 48)*OFN + kg];
            else             val = wv[(n - 96)*OFN + kg];
            sW[n][kk] = val;
        }
        __syncthreads();
        #pragma unroll 11
        for (int kk = 0; kk < 44; kk++) {
            float a0 = sA[2*ty][kk], a1 = sA[2*ty + 1][kk];
            #pragma unroll
            for (int j = 0; j < 9; j++) {
                float wv_ = sW[tx + 16*j][kk];
                acc[0][j] = fmaf(a0, wv_, acc[0][j]);
                acc[1][j] = fmaf(a1, wv_, acc[1][j]);
            }
        }
        __syncthreads();
    }
    #pragma unroll
    for (int r = 0; r < 2; r++)
        #pragma unroll
        for (int j = 0; j < 9; j++)
            g_qkv[(size_t)(m0 + 2*ty + r)*144 + tx + 16*j] = acc[r][j];
}

// ---------------- K6: sliding-window attention -----------------------------
// block = (b, 64-t tile); k/v windows + rel staged in smem
#define TTILE 64
__global__ void k_attn(const float* __restrict__ rel, float* __restrict__ a_out) {
    __shared__ float ks[TTILE + 30][49];
    __shared__ float vs[TTILE + 30][49];
    __shared__ float srel[MCN*KW];
    int b  = blockIdx.x / (TT / TTILE);
    int t0 = (blockIdx.x % (TT / TTILE)) * TTILE;

    for (int i = threadIdx.x; i < MCN*KW; i += 256) srel[i] = rel[i];
    for (int i = threadIdx.x; i < (TTILE + 30)*MCN; i += 256) {
        int row = i / MCN, col = i % MCN;
        int t = t0 + row - PADW;
        float kv = 0.f, vv = 0.f;
        if (t >= 0 && t < TT) {
            const float* p = g_qkv + ((size_t)b*TT + t)*144;
            kv = p[48 + col];
            vv = p[96 + col];
        }
        ks[row][col] = kv;
        vs[row][col] = vv;
    }
    __syncthreads();

    for (int item = threadIdx.x; item < TTILE*GN; item += 256) {
        int g  = item % GN;
        int tl = item / GN;
        int t = t0 + tl;
        int gd = g * DH;
        const float* qp = g_qkv + ((size_t)b*TT + t)*144 + gd;
        float q0 = qp[0], q1 = qp[1], q2 = qp[2], q3 = qp[3], q4 = qp[4], q5 = qp[5];

        float e[KW];
        float emax = -1e30f;
        #pragma unroll
        for (int kk = 0; kk < KW; kk++) {
            float s;
            s =          q0 * (ks[tl + kk][gd + 0] + srel[(gd + 0)*KW + kk]);
            s = fmaf(q1, (ks[tl + kk][gd + 1] + srel[(gd + 1)*KW + kk]), s);
            s = fmaf(q2, (ks[tl + kk][gd + 2] + srel[(gd + 2)*KW + kk]), s);
            s = fmaf(q3, (ks[tl + kk][gd + 3] + srel[(gd + 3)*KW + kk]), s);
            s = fmaf(q4, (ks[tl + kk][gd + 4] + srel[(gd + 4)*KW + kk]), s);
            s = fmaf(q5, (ks[tl + kk][gd + 5] + srel[(gd + 5)*KW + kk]), s);
            e[kk] = s;
            emax = fmaxf(emax, s);
        }
        float sum = 0.f;
        #pragma unroll
        for (int kk = 0; kk < KW; kk++) {
            e[kk] = __expf(e[kk] - emax);
            sum += e[kk];
        }
        float inv = 1.f / sum;
        float o0 = 0.f, o1 = 0.f, o2 = 0.f, o3 = 0.f, o4 = 0.f, o5 = 0.f;
        float* ap = a_out + (((size_t)b*TT + t)*GN + g)*KW;
        #pragma unroll
        for (int kk = 0; kk < KW; kk++) {
            float p = e[kk] * inv;
            ap[kk] = p;
            o0 = fmaf(p, vs[tl + kk][gd + 0], o0);
            o1 = fmaf(p, vs[tl + kk][gd + 1], o1);
            o2 = fmaf(p, vs[tl + kk][gd + 2], o2);
            o3 = fmaf(p, vs[tl + kk][gd + 3], o3);
            o4 = fmaf(p, vs[tl + kk][gd + 4], o4);
            o5 = fmaf(p, vs[tl + kk][gd + 5], o5);
        }
        float* op = g_out48 + ((size_t)b*TT + t)*MCN + gd;
        op[0] = o0; op[1] = o1; op[2] = o2; op[3] = o3; op[4] = o4; op[5] = o5;
    }
}

// ---------------- K7: LayerNorm(48) + linear(48->88) + sigmoid -------------
// one warp per row; 8 rows per block; lin_w staged in smem (stride 49)
__global__ void k_lnout(const float* __restrict__ lng, const float* __restrict__ lnb,
                        const float* __restrict__ lw, const float* __restrict__ lb,
                        float* __restrict__ out) {
    __shared__ float slw[OFN*49];
    __shared__ float sh[8][MCN];
    __shared__ float sg[MCN], sb[MCN], slb[OFN];
    for (int i = threadIdx.x; i < OFN*MCN; i += 256) {
        int n = i / MCN, j = i % MCN;
        slw[n*49 + j] = lw[i];
    }
    if (threadIdx.x < MCN) { sg[threadIdx.x] = lng[threadIdx.x]; sb[threadIdx.x] = lnb[threadIdx.x]; }
    if (threadIdx.x < OFN) slb[threadIdx.x] = lb[threadIdx.x];
    __syncthreads();

    int warp = threadIdx.x / 32, lane = threadIdx.x % 32;
    int row = blockIdx.x * 8 + warp;
    const float* xp = g_out48 + (size_t)row*MCN;
    float x0 = xp[lane];
    float x1 = (lane < 16) ? xp[lane + 32] : 0.f;
    float s  = x0 + x1;
    float s2 = x0*x0 + x1*x1;
    #pragma unroll
    for (int off = 16; off > 0; off >>= 1) {
        s  += __shfl_xor_sync(0xFFFFFFFFu, s,  off);
        s2 += __shfl_xor_sync(0xFFFFFFFFu, s2, off);
    }
    float mu = s * (1.f/48.f);
    float var = s2 * (1.f/48.f) - mu*mu;
    float rstd = rsqrtf(var + 1e-5f);
    sh[warp][lane] = (x0 - mu) * rstd * sg[lane] + sb[lane];
    if (lane < 16) sh[warp][lane + 32] = (x1 - mu) * rstd * sg[lane + 32] + sb[lane + 32];
    __syncwarp();

    #pragma unroll
    for (int jj = 0; jj < 3; jj++) {
        int n = lane + 32*jj;
        if (n < OFN) {
            float z = slb[n];
            #pragma unroll
            for (int j = 0; j < MCN; j++)
                z = fmaf(sh[warp][j], slw[n*49 + j], z);
            out[(size_t)row*OFN + n] = 1.f / (1.f + __expf(-z));
        }
    }
}

// ---------------- launch ---------------------------------------------------
extern "C" void kernel_launch(void* const* d_in, const int* in_sizes, int n_in,
                              void* d_out, int out_size) {
    const float* spec  = (const float*)d_in[0];
    const float* c1_w  = (const float*)d_in[1];
    const float* c1_b  = (const float*)d_in[2];
    const float* bn1_g = (const float*)d_in[3];
    const float* bn1_b = (const float*)d_in[4];
    const float* bn1_m = (const float*)d_in[5];
    const float* bn1_v = (const float*)d_in[6];
    const float* c2_w  = (const float*)d_in[7];
    const float* c2_b  = (const float*)d_in[8];
    const float* bn2_g = (const float*)d_in[9];
    const float* bn2_b = (const float*)d_in[10];
    const float* bn2_m = (const float*)d_in[11];
    const float* bn2_v = (const float*)d_in[12];
    const float* c3_w  = (const float*)d_in[13];
    const float* c3_b  = (const float*)d_in[14];
    const float* bn3_g = (const float*)d_in[15];
    const float* bn3_b = (const float*)d_in[16];
    const float* bn3_m = (const float*)d_in[17];
    const float* bn3_v = (const float*)d_in[18];
    const float* fc_w  = (const float*)d_in[19];
    const float* fc_b  = (const float*)d_in[20];
    const float* wq    = (const float*)d_in[21];
    const float* wk    = (const float*)d_in[22];
    const float* wv    = (const float*)d_in[23];
    const float* rel   = (const float*)d_in[24];
    const float* ln_g  = (const float*)d_in[25];
    const float* ln_b  = (const float*)d_in[26];
    const float* lin_w = (const float*)d_in[27];
    const float* lin_b = (const float*)d_in[28];

    float* out   = (float*)d_out;                 // frame_pred (B,T,88)
    float* a_out = out + FRAME_ELEMS;             // a (B,T,8,31)

    int n1 = BB*TT*FF;
    k_conv1<<<(n1 + 255)/256, 256>>>(spec, c1_w, c1_b, bn1_g, bn1_b, bn1_m, bn1_v);
    int n2 = BB*TT*F2;
    k_conv2pool<<<(n2 + 255)/256, 256>>>(c2_w, c2_b, bn2_g, bn2_b, bn2_m, bn2_v);
    int n3 = BB*TT*F3;
    k_conv3pool<<<(n3 + 255)/256, 256>>>(c3_w, c3_b, bn3_g, bn3_b, bn3_m, bn3_v);
    k_fc<<<(BB*TT)/128, 256>>>(fc_w, fc_b);
    k_qkv<<<(BB*TT)/32, 256>>>(wq, wk, wv);
    k_attn<<<BB*(TT/TTILE), 256>>>(rel, a_out);
    k_lnout<<<(BB*TT)/8, 256>>>(ln_g, ln_b, lin_w, lin_b, out);
}

// round 5
// speedup vs baseline: 1.1875x; 1.1875x over previous
#include <cuda_runtime.h>

#define BB 8
#define TT 2560
#define FF 229
#define C1N 5
#define C2N 11
#define F2 114
#define F3 57
#define FEAT 627       // C2N * F3
#define FEATP 640      // padded K for fc (float4-aligned)
#define OFN 88
#define MCN 48
#define GN 8
#define DH 6
#define KW 31
#define PADW 15
#define BNEPS 1e-5f
#define FRAME_ELEMS (BB*TT*OFN)

// ---------------- scratch (device globals; no allocation allowed) ----------
__device__ float g_y1[(size_t)BB*C1N*TT*FF];     // conv1 out  (B,C1,T,F)
__device__ float g_y2[(size_t)BB*C1N*TT*F2];     // conv2+pool (B,C1,T,F2)
__device__ float g_x627[(size_t)BB*TT*FEATP];    // conv3+pool, (B*T, 640) padded
__device__ float g_wfc[(size_t)OFN*FEATP];       // repacked fc_w (88, 640) padded
__device__ float g_x88[(size_t)BB*TT*OFN];       // fc out (B*T, 88)
__device__ float g_qkv[(size_t)BB*TT*144];       // q|k|v (B*T, 144)
__device__ float g_out48[(size_t)BB*TT*MCN];     // attention out (B*T, 48)

// ---------------- K0: repack fc weights into padded layout -----------------
__global__ void k_repack_w(const float* __restrict__ fw) {
    int idx = blockIdx.x * blockDim.x + threadIdx.x;
    if (idx >= OFN*FEATP) return;
    int n = idx / FEATP, k = idx % FEATP;
    g_wfc[idx] = (k < FEAT) ? fw[n*FEAT + k] : 0.f;
}

// ---------------- K1: conv1(1->5) + BN + ReLU ------------------------------
__global__ void k_conv1(const float* __restrict__ spec, const float* __restrict__ w,
                        const float* __restrict__ cb, const float* __restrict__ bg,
                        const float* __restrict__ bbt, const float* __restrict__ bm,
                        const float* __restrict__ bv) {
    __shared__ float sw[C1N*9];
    __shared__ float ssc[C1N], sbi[C1N];
    for (int i = threadIdx.x; i < C1N*9; i += blockDim.x) sw[i] = w[i];
    if (threadIdx.x < C1N) {
        float sc = bg[threadIdx.x] * rsqrtf(bv[threadIdx.x] + BNEPS);
        ssc[threadIdx.x] = sc;
        sbi[threadIdx.x] = (cb[threadIdx.x] - bm[threadIdx.x]) * sc + bbt[threadIdx.x];
    }
    __syncthreads();
    int idx = blockIdx.x * blockDim.x + threadIdx.x;
    if (idx >= BB*TT*FF) return;
    int f = idx % FF;
    int t = (idx / FF) % TT;
    int b = idx / (FF*TT);
    const float* sp = spec + (size_t)b * TT * FF;
    float in[3][3];
    #pragma unroll
    for (int dt = 0; dt < 3; dt++) {
        int tt = t + dt - 1;
        #pragma unroll
        for (int df = 0; df < 3; df++) {
            int ff = f + df - 1;
            in[dt][df] = (tt >= 0 && tt < TT && ff >= 0 && ff < FF) ? sp[tt*FF + ff] : 0.f;
        }
    }
    #pragma unroll
    for (int c = 0; c < C1N; c++) {
        float acc = 0.f;
        #pragma unroll
        for (int k9 = 0; k9 < 9; k9++)
            acc = fmaf(in[k9/3][k9%3], sw[c*9 + k9], acc);
        float val = acc * ssc[c] + sbi[c];
        g_y1[(((size_t)b*C1N + c)*TT + t)*FF + f] = fmaxf(val, 0.f);
    }
}

// ---------------- K2: conv2(5->5) + BN + ReLU + maxpool(W/2) ---------------
__global__ void k_conv2pool(const float* __restrict__ w, const float* __restrict__ cb,
                            const float* __restrict__ bg, const float* __restrict__ bbt,
                            const float* __restrict__ bm, const float* __restrict__ bv) {
    __shared__ float sw[C1N*C1N*9];
    __shared__ float ssc[C1N], sbi[C1N];
    for (int i = threadIdx.x; i < C1N*C1N*9; i += blockDim.x) sw[i] = w[i];
    if (threadIdx.x < C1N) {
        float sc = bg[threadIdx.x] * rsqrtf(bv[threadIdx.x] + BNEPS);
        ssc[threadIdx.x] = sc;
        sbi[threadIdx.x] = (cb[threadIdx.x] - bm[threadIdx.x]) * sc + bbt[threadIdx.x];
    }
    __syncthreads();
    int idx = blockIdx.x * blockDim.x + threadIdx.x;
    if (idx >= BB*TT*F2) return;
    int fp = idx % F2;
    int t = (idx / F2) % TT;
    int b = idx / (F2*TT);
    float acc0[C1N], acc1[C1N];
    #pragma unroll
    for (int c = 0; c < C1N; c++) { acc0[c] = 0.f; acc1[c] = 0.f; }
    #pragma unroll
    for (int ci = 0; ci < C1N; ci++) {
        const float* base = g_y1 + ((size_t)b*C1N + ci)*TT*FF;
        float patch[3][4];
        #pragma unroll
        for (int dt = 0; dt < 3; dt++) {
            int tt = t + dt - 1;
            #pragma unroll
            for (int df = 0; df < 4; df++) {
                int ff = 2*fp + df - 1;
                patch[dt][df] = (tt >= 0 && tt < TT && ff >= 0 && ff < FF) ? base[tt*FF + ff] : 0.f;
            }
        }
        #pragma unroll
        for (int co = 0; co < C1N; co++) {
            const float* wp = &sw[(co*C1N + ci)*9];
            #pragma unroll
            for (int dt = 0; dt < 3; dt++) {
                #pragma unroll
                for (int df = 0; df < 3; df++) {
                    float wv_ = wp[dt*3 + df];
                    acc0[co] = fmaf(patch[dt][df],     wv_, acc0[co]);
                    acc1[co] = fmaf(patch[dt][df + 1], wv_, acc1[co]);
                }
            }
        }
    }
    #pragma unroll
    for (int co = 0; co < C1N; co++) {
        float v0 = fmaxf(acc0[co]*ssc[co] + sbi[co], 0.f);
        float v1 = fmaxf(acc1[co]*ssc[co] + sbi[co], 0.f);
        g_y2[(((size_t)b*C1N + co)*TT + t)*F2 + fp] = fmaxf(v0, v1);
    }
}

// ---------------- K3: conv3(5->11) + BN + ReLU + maxpool + transpose -------
__global__ void k_conv3pool(const float* __restrict__ w, const float* __restrict__ cb,
                            const float* __restrict__ bg, const float* __restrict__ bbt,
                            const float* __restrict__ bm, const float* __restrict__ bv) {
    __shared__ float sw[C2N*C1N*9];   // 495 floats
    __shared__ float ssc[C2N], sbi[C2N];
    for (int i = threadIdx.x; i < C2N*C1N*9; i += blockDim.x) sw[i] = w[i];
    if (threadIdx.x < C2N) {
        float sc = bg[threadIdx.x] * rsqrtf(bv[threadIdx.x] + BNEPS);
        ssc[threadIdx.x] = sc;
        sbi[threadIdx.x] = (cb[threadIdx.x] - bm[threadIdx.x]) * sc + bbt[threadIdx.x];
    }
    __syncthreads();
    int idx = blockIdx.x * blockDim.x + threadIdx.x;
    if (idx >= BB*TT*F3) return;
    int fp = idx % F3;
    int t = (idx / F3) % TT;
    int b = idx / (F3*TT);
    float acc0[C2N], acc1[C2N];
    #pragma unroll
    for (int c = 0; c < C2N; c++) { acc0[c] = 0.f; acc1[c] = 0.f; }
    #pragma unroll
    for (int ci = 0; ci < C1N; ci++) {
        const float* base = g_y2 + ((size_t)b*C1N + ci)*TT*F2;
        float patch[3][4];
        #pragma unroll
        for (int dt = 0; dt < 3; dt++) {
            int tt = t + dt - 1;
            #pragma unroll
            for (int df = 0; df < 4; df++) {
                int ff = 2*fp + df - 1;
                patch[dt][df] = (tt >= 0 && tt < TT && ff >= 0 && ff < F2) ? base[tt*F2 + ff] : 0.f;
            }
        }
        #pragma unroll
        for (int co = 0; co < C2N; co++) {
            const float* wp = &sw[(co*C1N + ci)*9];
            #pragma unroll
            for (int dt = 0; dt < 3; dt++) {
                #pragma unroll
                for (int df = 0; df < 3; df++) {
                    float wv_ = wp[dt*3 + df];
                    acc0[co] = fmaf(patch[dt][df],     wv_, acc0[co]);
                    acc1[co] = fmaf(patch[dt][df + 1], wv_, acc1[co]);
                }
            }
        }
    }
    size_t rowbase = ((size_t)b*TT + t)*FEATP;
    #pragma unroll
    for (int co = 0; co < C2N; co++) {
        float v0 = fmaxf(acc0[co]*ssc[co] + sbi[co], 0.f);
        float v1 = fmaxf(acc1[co]*ssc[co] + sbi[co], 0.f);
        g_x627[rowbase + co*F3 + fp] = fmaxf(v0, v1);
    }
    // zero the 13 pad columns (627..639) of this row
    if (fp < FEATP - FEAT) g_x627[rowbase + FEAT + fp] = 0.f;
}

// ---------------- K4: fc GEMM (20480 x 640p) @ (640p x 88) + bias ----------
// 64-row M tiles (320 blocks), 128 threads, 4x11 per-thread tile,
// double-buffered smem, float4 global loads.
__global__ __launch_bounds__(128) void k_fc(const float* __restrict__ bias) {
    __shared__ float sA[2][64][33];
    __shared__ float sW[2][OFN][33];
    const int m0 = blockIdx.x * 64;
    const int tid = threadIdx.x;
    const int tx = tid % 8;       // cols tx + 8*j, j=0..10
    const int ty = tid / 8;       // 0..15 -> rows 4*ty .. 4*ty+3

    float acc[4][11];
    #pragma unroll
    for (int r = 0; r < 4; r++)
        #pragma unroll
        for (int j = 0; j < 11; j++) acc[r][j] = 0.f;

    float4 pa[4];   // A: 64 rows x 32 k = 512 float4, 4 per thread
    float4 pw[6];   // W: 88 rows x 32 k = 704 float4, 5.5 per thread

    // ---- preload tile 0 ----
    {
        const int k0 = 0;
        #pragma unroll
        for (int u = 0; u < 4; u++) {
            int id = tid + 128*u, row = id >> 3, ks = id & 7;
            pa[u] = *(const float4*)(g_x627 + (size_t)(m0 + row)*FEATP + k0 + 4*ks);
        }
        #pragma unroll
        for (int u = 0; u < 6; u++) {
            int id = tid + 128*u;
            if (id < 704) {
                int row = id >> 3, ks = id & 7;
                pw[u] = *(const float4*)(g_wfc + (size_t)row*FEATP + k0 + 4*ks);
            }
        }
        #pragma unroll
        for (int u = 0; u < 4; u++) {
            int id = tid + 128*u, row = id >> 3, ks = id & 7;
            sA[0][row][4*ks+0] = pa[u].x; sA[0][row][4*ks+1] = pa[u].y;
            sA[0][row][4*ks+2] = pa[u].z; sA[0][row][4*ks+3] = pa[u].w;
        }
        #pragma unroll
        for (int u = 0; u < 6; u++) {
            int id = tid + 128*u;
            if (id < 704) {
                int row = id >> 3, ks = id & 7;
                sW[0][row][4*ks+0] = pw[u].x; sW[0][row][4*ks+1] = pw[u].y;
                sW[0][row][4*ks+2] = pw[u].z; sW[0][row][4*ks+3] = pw[u].w;
            }
        }
    }
    __syncthreads();

    const int NIT = FEATP / 32;   // 20
    for (int it = 0; it < NIT; it++) {
        const int buf = it & 1;
        // prefetch next tile into registers (overlaps with compute)
        if (it + 1 < NIT) {
            const int k0 = (it + 1) * 32;
            #pragma unroll
            for (int u = 0; u < 4; u++) {
                int id = tid + 128*u, row = id >> 3, ks = id & 7;
                pa[u] = *(const float4*)(g_x627 + (size_t)(m0 + row)*FEATP + k0 + 4*ks);
            }
            #pragma unroll
            for (int u = 0; u < 6; u++) {
                int id = tid + 128*u;
                if (id < 704) {
                    int row = id >> 3, ks = id & 7;
                    pw[u] = *(const float4*)(g_wfc + (size_t)row*FEATP + k0 + 4*ks);
                }
            }
        }
        // compute on current buffer
        #pragma unroll 8
        for (int kk = 0; kk < 32; kk++) {
            float a0 = sA[buf][4*ty+0][kk];
            float a1 = sA[buf][4*ty+1][kk];
            float a2 = sA[buf][4*ty+2][kk];
            float a3 = sA[buf][4*ty+3][kk];
            #pragma unroll
            for (int j = 0; j < 11; j++) {
                float wv_ = sW[buf][tx + 8*j][kk];
                acc[0][j] = fmaf(a0, wv_, acc[0][j]);
                acc[1][j] = fmaf(a1, wv_, acc[1][j]);
                acc[2][j] = fmaf(a2, wv_, acc[2][j]);
                acc[3][j] = fmaf(a3, wv_, acc[3][j]);
            }
        }
        // store prefetched tile into the other buffer
        if (it + 1 < NIT) {
            const int nb = buf ^ 1;
            #pragma unroll
            for (int u = 0; u < 4; u++) {
                int id = tid + 128*u, row = id >> 3, ks = id & 7;
                sA[nb][row][4*ks+0] = pa[u].x; sA[nb][row][4*ks+1] = pa[u].y;
                sA[nb][row][4*ks+2] = pa[u].z; sA[nb][row][4*ks+3] = pa[u].w;
            }
            #pragma unroll
            for (int u = 0; u < 6; u++) {
                int id = tid + 128*u;
                if (id < 704) {
                    int row = id >> 3, ks = id & 7;
                    sW[nb][row][4*ks+0] = pw[u].x; sW[nb][row][4*ks+1] = pw[u].y;
                    sW[nb][row][4*ks+2] = pw[u].z; sW[nb][row][4*ks+3] = pw[u].w;
                }
            }
        }
        __syncthreads();
    }

    #pragma unroll
    for (int j = 0; j < 11; j++) {
        float bj = bias[tx + 8*j];
        #pragma unroll
        for (int r = 0; r < 4; r++)
            g_x88[(size_t)(m0 + 4*ty + r)*OFN + tx + 8*j] = acc[r][j] + bj;
    }
}

// ---------------- K5: qkv GEMM (20480 x 88) @ (88 x 144) -------------------
__global__ void k_qkv(const float* __restrict__ wq, const float* __restrict__ wk,
                      const float* __restrict__ wv) {
    __shared__ float sA[32][45];
    __shared__ float sW[144][45];
    int m0 = blockIdx.x * 32;
    int tx = threadIdx.x % 16;   // cols tx + 16*j, j=0..8
    int ty = threadIdx.x / 16;   // 0..15 -> rows 2*ty, 2*ty+1
    float acc[2][9];
    #pragma unroll
    for (int r = 0; r < 2; r++)
        #pragma unroll
        for (int j = 0; j < 9; j++) acc[r][j] = 0.f;

    for (int k0 = 0; k0 < OFN; k0 += 44) {
        for (int i = threadIdx.x; i < 32*44; i += 256) {
            int rr = i / 44, kk = i % 44;
            sA[rr][kk] = g_x88[(size_t)(m0 + rr)*OFN + k0 + kk];
        }
        for (int i = threadIdx.x; i < 144*44; i += 256) {
            int n = i / 44, kk = i % 44;
            int kg = k0 + kk;
            float val;
            if (n < 48)      val = wq[n*OFN + kg];
            else if (n < 96) val = wk[(n - 48)*OFN + kg];
            else             val = wv[(n - 96)*OFN + kg];
            sW[n][kk] = val;
        }
        __syncthreads();
        #pragma unroll 11
        for (int kk = 0; kk < 44; kk++) {
            float a0 = sA[2*ty][kk], a1 = sA[2*ty + 1][kk];
            #pragma unroll
            for (int j = 0; j < 9; j++) {
                float wv_ = sW[tx + 16*j][kk];
                acc[0][j] = fmaf(a0, wv_, acc[0][j]);
                acc[1][j] = fmaf(a1, wv_, acc[1][j]);
            }
        }
        __syncthreads();
    }
    #pragma unroll
    for (int r = 0; r < 2; r++)
        #pragma unroll
        for (int j = 0; j < 9; j++)
            g_qkv[(size_t)(m0 + 2*ty + r)*144 + tx + 16*j] = acc[r][j];
}

// ---------------- K6: sliding-window attention -----------------------------
#define TTILE 64
__global__ void k_attn(const float* __restrict__ rel, float* __restrict__ a_out) {
    __shared__ float ks[TTILE + 30][49];
    __shared__ float vs[TTILE + 30][49];
    __shared__ float srel[MCN*KW];
    int b  = blockIdx.x / (TT / TTILE);
    int t0 = (blockIdx.x % (TT / TTILE)) * TTILE;

    for (int i = threadIdx.x; i < MCN*KW; i += 256) srel[i] = rel[i];
    for (int i = threadIdx.x; i < (TTILE + 30)*MCN; i += 256) {
        int row = i / MCN, col = i % MCN;
        int t = t0 + row - PADW;
        float kv = 0.f, vv = 0.f;
        if (t >= 0 && t < TT) {
            const float* p = g_qkv + ((size_t)b*TT + t)*144;
            kv = p[48 + col];
            vv = p[96 + col];
        }
        ks[row][col] = kv;
        vs[row][col] = vv;
    }
    __syncthreads();

    for (int item = threadIdx.x; item < TTILE*GN; item += 256) {
        int g  = item % GN;
        int tl = item / GN;
        int t = t0 + tl;
        int gd = g * DH;
        const float* qp = g_qkv + ((size_t)b*TT + t)*144 + gd;
        float q0 = qp[0], q1 = qp[1], q2 = qp[2], q3 = qp[3], q4 = qp[4], q5 = qp[5];

        float e[KW];
        float emax = -1e30f;
        #pragma unroll
        for (int kk = 0; kk < KW; kk++) {
            float s;
            s =          q0 * (ks[tl + kk][gd + 0] + srel[(gd + 0)*KW + kk]);
            s = fmaf(q1, (ks[tl + kk][gd + 1] + srel[(gd + 1)*KW + kk]), s);
            s = fmaf(q2, (ks[tl + kk][gd + 2] + srel[(gd + 2)*KW + kk]), s);
            s = fmaf(q3, (ks[tl + kk][gd + 3] + srel[(gd + 3)*KW + kk]), s);
            s = fmaf(q4, (ks[tl + kk][gd + 4] + srel[(gd + 4)*KW + kk]), s);
            s = fmaf(q5, (ks[tl + kk][gd + 5] + srel[(gd + 5)*KW + kk]), s);
            e[kk] = s;
            emax = fmaxf(emax, s);
        }
        float sum = 0.f;
        #pragma unroll
        for (int kk = 0; kk < KW; kk++) {
            e[kk] = __expf(e[kk] - emax);
            sum += e[kk];
        }
        float inv = 1.f / sum;
        float o0 = 0.f, o1 = 0.f, o2 = 0.f, o3 = 0.f, o4 = 0.f, o5 = 0.f;
        float* ap = a_out + (((size_t)b*TT + t)*GN + g)*KW;
        #pragma unroll
        for (int kk = 0; kk < KW; kk++) {
            float p = e[kk] * inv;
            ap[kk] = p;
            o0 = fmaf(p, vs[tl + kk][gd + 0], o0);
            o1 = fmaf(p, vs[tl + kk][gd + 1], o1);
            o2 = fmaf(p, vs[tl + kk][gd + 2], o2);
            o3 = fmaf(p, vs[tl + kk][gd + 3], o3);
            o4 = fmaf(p, vs[tl + kk][gd + 4], o4);
            o5 = fmaf(p, vs[tl + kk][gd + 5], o5);
        }
        float* op = g_out48 + ((size_t)b*TT + t)*MCN + gd;
        op[0] = o0; op[1] = o1; op[2] = o2; op[3] = o3; op[4] = o4; op[5] = o5;
    }
}

// ---------------- K7: LayerNorm(48) + linear(48->88) + sigmoid -------------
__global__ void k_lnout(const float* __restrict__ lng, const float* __restrict__ lnb,
                        const float* __restrict__ lw, const float* __restrict__ lb,
                        float* __restrict__ out) {
    __shared__ float slw[OFN*49];
    __shared__ float sh[8][MCN];
    __shared__ float sg[MCN], sb[MCN], slb[OFN];
    for (int i = threadIdx.x; i < OFN*MCN; i += 256) {
        int n = i / MCN, j = i % MCN;
        slw[n*49 + j] = lw[i];
    }
    if (threadIdx.x < MCN) { sg[threadIdx.x] = lng[threadIdx.x]; sb[threadIdx.x] = lnb[threadIdx.x]; }
    if (threadIdx.x < OFN) slb[threadIdx.x] = lb[threadIdx.x];
    __syncthreads();

    int warp = threadIdx.x / 32, lane = threadIdx.x % 32;
    int row = blockIdx.x * 8 + warp;
    const float* xp = g_out48 + (size_t)row*MCN;
    float x0 = xp[lane];
    float x1 = (lane < 16) ? xp[lane + 32] : 0.f;
    float s  = x0 + x1;
    float s2 = x0*x0 + x1*x1;
    #pragma unroll
    for (int off = 16; off > 0; off >>= 1) {
        s  += __shfl_xor_sync(0xFFFFFFFFu, s,  off);
        s2 += __shfl_xor_sync(0xFFFFFFFFu, s2, off);
    }
    float mu = s * (1.f/48.f);
    float var = s2 * (1.f/48.f) - mu*mu;
    float rstd = rsqrtf(var + 1e-5f);
    sh[warp][lane] = (x0 - mu) * rstd * sg[lane] + sb[lane];
    if (lane < 16) sh[warp][lane + 32] = (x1 - mu) * rstd * sg[lane + 32] + sb[lane + 32];
    __syncwarp();

    #pragma unroll
    for (int jj = 0; jj < 3; jj++) {
        int n = lane + 32*jj;
        if (n < OFN) {
            float z = slb[n];
            #pragma unroll
            for (int j = 0; j < MCN; j++)
                z = fmaf(sh[warp][j], slw[n*49 + j], z);
            out[(size_t)row*OFN + n] = 1.f / (1.f + __expf(-z));
        }
    }
}

// ---------------- launch ---------------------------------------------------
extern "C" void kernel_launch(void* const* d_in, const int* in_sizes, int n_in,
                              void* d_out, int out_size) {
    const float* spec  = (const float*)d_in[0];
    const float* c1_w  = (const float*)d_in[1];
    const float* c1_b  = (const float*)d_in[2];
    const float* bn1_g = (const float*)d_in[3];
    const float* bn1_b = (const float*)d_in[4];
    const float* bn1_m = (const float*)d_in[5];
    const float* bn1_v = (const float*)d_in[6];
    const float* c2_w  = (const float*)d_in[7];
    const float* c2_b  = (const float*)d_in[8];
    const float* bn2_g = (const float*)d_in[9];
    const float* bn2_b = (const float*)d_in[10];
    const float* bn2_m = (const float*)d_in[11];
    const float* bn2_v = (const float*)d_in[12];
    const float* c3_w  = (const float*)d_in[13];
    const float* c3_b  = (const float*)d_in[14];
    const float* bn3_g = (const float*)d_in[15];
    const float* bn3_b = (const float*)d_in[16];
    const float* bn3_m = (const float*)d_in[17];
    const float* bn3_v = (const float*)d_in[18];
    const float* fc_w  = (const float*)d_in[19];
    const float* fc_b  = (const float*)d_in[20];
    const float* wq    = (const float*)d_in[21];
    const float* wk    = (const float*)d_in[22];
    const float* wv    = (const float*)d_in[23];
    const float* rel   = (const float*)d_in[24];
    const float* ln_g  = (const float*)d_in[25];
    const float* ln_b  = (const float*)d_in[26];
    const float* lin_w = (const float*)d_in[27];
    const float* lin_b = (const float*)d_in[28];

    float* out   = (float*)d_out;                 // frame_pred (B,T,88)
    float* a_out = out + FRAME_ELEMS;             // a (B,T,8,31)

    k_repack_w<<<(OFN*FEATP + 255)/256, 256>>>(fc_w);
    int n1 = BB*TT*FF;
    k_conv1<<<(n1 + 255)/256, 256>>>(spec, c1_w, c1_b, bn1_g, bn1_b, bn1_m, bn1_v);
    int n2 = BB*TT*F2;
    k_conv2pool<<<(n2 + 255)/256, 256>>>(c2_w, c2_b, bn2_g, bn2_b, bn2_m, bn2_v);
    int n3 = BB*TT*F3;
    k_conv3pool<<<(n3 + 255)/256, 256>>>(c3_w, c3_b, bn3_g, bn3_b, bn3_m, bn3_v);
    k_fc<<<(BB*TT)/64, 128>>>(fc_b);
    k_qkv<<<(BB*TT)/32, 256>>>(wq, wk, wv);
    k_attn<<<BB*(TT/TTILE), 256>>>(rel, a_out);
    k_lnout<<<(BB*TT)/8, 256>>>(ln_g, ln_b, lin_w, lin_b, out);
}